// round 6
// baseline (speedup 1.0000x reference)
#include <cuda_runtime.h>
#include <cstdint>

#define N_NODES 131072
#define C_DIM   64
#define K_NEI   27
#define B_DIM   8
#define EMB_DIM 512
#define GN_EPS  1e-5f

// ---------------- scratch (device globals; no allocation allowed) -----------
__device__ float  g_h1[N_NODES * C_DIM];
__device__ float  g_h2[N_NODES * C_DIM];
__device__ float2 g_w1f[K_NEI * 2048];     // W1 in B-fragment order (tf32-rounded)
__device__ float2 g_w2f[K_NEI * 2048];     // W2 in B-fragment order
__device__ float  g_sum[B_DIM * C_DIM];
__device__ float  g_ssq[B_DIM * C_DIM];
__device__ float  g_cnt[B_DIM];
__device__ float  g_scale[B_DIM * C_DIM];
__device__ float  g_shift[B_DIM * C_DIM];
__device__ float  g_tvec[B_DIM * C_DIM];

// ---------------- helpers ----------------------------------------------------
__device__ __forceinline__ uint32_t smem_u32(const void* p) {
    uint32_t a;
    asm("{ .reg .u64 t; cvta.to.shared.u64 t, %1; cvt.u32.u64 %0, t; }" : "=r"(a) : "l"(p));
    return a;
}
__device__ __forceinline__ void cp16(uint32_t dst, const void* src) {
    asm volatile("cp.async.cg.shared.global [%0], [%1], 16;" :: "r"(dst), "l"(src) : "memory");
}
__device__ __forceinline__ void cp_commit() {
    asm volatile("cp.async.commit_group;" ::: "memory");
}
template <int N>
__device__ __forceinline__ void cp_wait() {
    asm volatile("cp.async.wait_group %0;" :: "n"(N) : "memory");
}
__device__ __forceinline__ float tf32r(float v) {
    uint32_t r;
    asm("cvt.rna.tf32.f32 %0, %1;" : "=r"(r) : "f"(v));
    return __uint_as_float(r);
}
__device__ __forceinline__ void mma_tf32(float* d, uint32_t a0, uint32_t a1, uint32_t a2,
                                         uint32_t a3, uint32_t b0, uint32_t b1) {
    asm volatile(
        "mma.sync.aligned.m16n8k8.row.col.f32.tf32.tf32.f32 "
        "{%0,%1,%2,%3}, {%4,%5,%6,%7}, {%8,%9}, {%0,%1,%2,%3};"
        : "+f"(d[0]), "+f"(d[1]), "+f"(d[2]), "+f"(d[3])
        : "r"(a0), "r"(a1), "r"(a2), "r"(a3), "r"(b0), "r"(b1));
}
__device__ __forceinline__ float silu_f(float v) { return v / (1.0f + __expf(-v)); }

// ---------------- GN helper kernels ------------------------------------------
__global__ void zero_kernel(float* gsum, float* gssq, float* gcnt) {
    int i = threadIdx.x;
    gsum[i] = 0.0f; gssq[i] = 0.0f;
    if (i < B_DIM) gcnt[i] = 0.0f;
}

__global__ void stats_kernel(const float* __restrict__ in, const int* __restrict__ bid,
                             float* __restrict__ gsum, float* __restrict__ gssq,
                             float* __restrict__ gcnt, int do_cnt) {
    const int NPB = 512;
    int c = threadIdx.x & 63, r = threadIdx.x >> 6;
    int base = blockIdx.x * NPB;
    float s = 0.0f, ss = 0.0f, cl = 0.0f;
    int cur = bid[base + r];
    for (int i = 0; i < NPB / 4; i++) {
        int n = base + i * 4 + r;
        int b = bid[n];
        if (b != cur) {
            atomicAdd(&gsum[cur * 64 + c], s);
            atomicAdd(&gssq[cur * 64 + c], ss);
            if (do_cnt && c == 0) atomicAdd(&gcnt[cur], cl);
            s = 0.0f; ss = 0.0f; cl = 0.0f; cur = b;
        }
        float v = in[(size_t)n * 64 + c];
        s += v; ss += v * v; cl += 1.0f;
    }
    atomicAdd(&gsum[cur * 64 + c], s);
    atomicAdd(&gssq[cur * 64 + c], ss);
    if (do_cnt && c == 0) atomicAdd(&gcnt[cur], cl);
}

__global__ void finalize_kernel(float* __restrict__ gsum, float* __restrict__ gssq,
                                const float* __restrict__ gcnt,
                                const float* __restrict__ gamma, const float* __restrict__ beta,
                                float* __restrict__ scale, float* __restrict__ shift,
                                int zero_after) {
    int i = threadIdx.x;
    int b = i >> 6, c = i & 63;
    int g0 = c & ~1;
    float denom = gcnt[b] * 2.0f;
    float m = (gsum[b * 64 + g0] + gsum[b * 64 + g0 + 1]) / denom;
    float v = (gssq[b * 64 + g0] + gssq[b * 64 + g0 + 1]) / denom - m * m;
    float rs = rsqrtf(v + GN_EPS);
    float sc = gamma[c] * rs;
    scale[i] = sc;
    shift[i] = beta[c] - m * sc;
    if (zero_after) {
        __syncthreads();
        gsum[i] = 0.0f;
        gssq[i] = 0.0f;
    }
}

__global__ void normact_kernel(const float4* __restrict__ in, const int* __restrict__ bid,
                               const float4* __restrict__ scale, const float4* __restrict__ shift,
                               float4* __restrict__ out) {
    int idx = blockIdx.x * blockDim.x + threadIdx.x;
    int n = idx >> 4, q = idx & 15;
    int b = bid[n];
    float4 v = in[idx];
    float4 sc = scale[b * 16 + q];
    float4 sh = shift[b * 16 + q];
    float4 r;
    r.x = tf32r(silu_f(v.x * sc.x + sh.x));
    r.y = tf32r(silu_f(v.y * sc.y + sh.y));
    r.z = tf32r(silu_f(v.z * sc.z + sh.z));
    r.w = tf32r(silu_f(v.w * sc.w + sh.w));
    out[idx] = r;
}

__global__ void time_kernel(const float* __restrict__ emb, const float* __restrict__ Wt,
                            const float* __restrict__ bt, float* __restrict__ tout) {
    __shared__ float se[B_DIM * EMB_DIM];
    int t = threadIdx.x;
    for (int i = t; i < B_DIM * EMB_DIM; i += 512) se[i] = silu_f(emb[i]);
    __syncthreads();
    int b = t >> 6, co = t & 63;
    float acc = bt[co];
    const float* e = se + b * EMB_DIM;
    #pragma unroll 8
    for (int k = 0; k < EMB_DIM; k++) acc += e[k] * Wt[k * 64 + co];
    tout[t] = acc;
}

// ---------------- weight prep: W[k][ci][co] -> B-fragment order (tf32) -------
__global__ void prep_w_kernel(const float* __restrict__ W, float2* __restrict__ Wf) {
    int i = blockIdx.x * 256 + threadIdx.x;      // over K_NEI*2048
    if (i >= K_NEI * 2048) return;
    int k = i >> 11;
    int r = i & 2047;
    int grp = r >> 5, lane = r & 31;
    int s = grp >> 3, c = grp & 7;
    int ci = s * 8 + (lane & 3);
    int co = c * 8 + (lane >> 2);
    const float* wk = W + (size_t)k * 4096;
    float2 v;
    v.x = tf32r(wk[ci * 64 + co]);
    v.y = tf32r(wk[(ci + 4) * 64 + co]);
    Wf[i] = v;
}

// ---------------- tf32 mma.sync gather-conv ----------------------------------
// 256 nodes/block, 256 threads (8 warps), each warp computes 32 rows x 64 co
// (two m16 tiles amortize every weight fragment LDS 2x). Warp-coalesced
// cp.async gather staging; XOR-swizzled unpadded A buffer (stride 64 floats).
#define TN        256
#define XS_FLOATS (TN * 64)                   // 16384 floats / buffer (64KB)
#define WS_OFF    0                           // float2 ws[2][2048] : 32KB
#define XS_OFF    32768                       // float  xs[2][16384]: 128KB
#define NB_OFF    (32768 + 131072)            // int snb[27][256]   : 27648B
#define SM_TOTAL  (NB_OFF + K_NEI * TN * 4)   // 191488

__global__ void __launch_bounds__(256, 1) conv_mma_kernel(
    const float* __restrict__ h, const int* __restrict__ neigh,
    const float2* __restrict__ wf, const float* __restrict__ bias,
    const float* __restrict__ tvec, const int* __restrict__ bid,
    const float* __restrict__ resid, float* __restrict__ out)
{
    extern __shared__ char smem[];
    float2* ws = reinterpret_cast<float2*>(smem + WS_OFF);
    float*  xs = reinterpret_cast<float*>(smem + XS_OFF);
    int*    snb = reinterpret_cast<int*>(smem + NB_OFF);
    const uint32_t ws_sm = smem_u32(smem + WS_OFF);
    const uint32_t xs_sm = smem_u32(smem + XS_OFF);

    const int t = threadIdx.x;
    const int w = t >> 5, l = t & 31;
    const int base = blockIdx.x * TN;

    // ---- transpose-load neighbor ids: snb[k][row] (coalesced gmem read) ----
    {
        const int* nsrc = neigh + (size_t)base * K_NEI;
        for (int i = t; i < TN * K_NEI; i += 256) {
            int node = i / K_NEI;
            int kk = i - node * K_NEI;
            snb[kk * TN + node] = nsrc[i];
        }
    }
    __syncthreads();

    float acc[2][8][4];
    #pragma unroll
    for (int ti = 0; ti < 2; ti++)
        #pragma unroll
        for (int c = 0; c < 8; c++)
            #pragma unroll
            for (int j = 0; j < 4; j++) acc[ti][c][j] = 0.0f;

    const int half  = l >> 4;      // 0/1: which of the 2 rows in this warp-op
    const int chunk = l & 15;      // 16B chunk within the 256B row

    // ---- stage k into buffer (k&1): warp-coalesced ------------------------
    auto issue = [&](int k) {
        const int buf = k & 1;
        // weights: 16KB linear, 4x16B per thread (contiguous per warp)
        {
            const char* src = reinterpret_cast<const char*>(wf + (size_t)k * 2048) + t * 64;
            uint32_t dst = ws_sm + buf * 16384 + t * 64;
            #pragma unroll
            for (int j = 0; j < 4; j++) cp16(dst + j * 16, src + j * 16);
        }
        // gather: warp w stages rows w*32..w*32+31; 2 rows per instruction
        {
            const int* nbk = snb + k * TN;
            #pragma unroll
            for (int i = 0; i < 16; i++) {
                int row = w * 32 + 2 * i + half;
                int nbv = nbk[row];
                const char* src = reinterpret_cast<const char*>(h + (size_t)nbv * 64)
                                  + chunk * 16;
                uint32_t dst = xs_sm + buf * 65536 + row * 256
                               + ((chunk ^ (row & 7)) << 4);
                cp16(dst, src);
            }
        }
        cp_commit();
    };

    issue(0);
    issue(1);

    const int g = l >> 2, tig = l & 3;

    for (int k = 0; k < K_NEI; k++) {
        cp_wait<1>();          // group k complete
        __syncthreads();

        const int buf = k & 1;
        const float*  rp0 = xs + buf * XS_FLOATS + (w * 32) * 64 + g * 64;
        const float*  rp1 = rp0 + 1024;         // +16 rows
        const float2* wb = ws + buf * 2048;

        #pragma unroll
        for (int s = 0; s < 8; s++) {
            int ph  = (s * 8 + tig) ^ (g << 2);
            int ph2 = ph ^ 4;
            uint32_t a00 = __float_as_uint(rp0[ph]);
            uint32_t a02 = __float_as_uint(rp0[ph2]);
            uint32_t a01 = __float_as_uint(rp0[512 + ph]);
            uint32_t a03 = __float_as_uint(rp0[512 + ph2]);
            uint32_t a10 = __float_as_uint(rp1[ph]);
            uint32_t a12 = __float_as_uint(rp1[ph2]);
            uint32_t a11 = __float_as_uint(rp1[512 + ph]);
            uint32_t a13 = __float_as_uint(rp1[512 + ph2]);
            #pragma unroll
            for (int c = 0; c < 8; c++) {
                float2 b = wb[(s * 8 + c) * 32 + l];
                uint32_t b0 = __float_as_uint(b.x), b1 = __float_as_uint(b.y);
                mma_tf32(acc[0][c], a00, a01, a02, a03, b0, b1);
                mma_tf32(acc[1][c], a10, a11, a12, a13, b0, b1);
            }
        }
        __syncthreads();       // all warps done with buf before refill
        if (k + 2 < K_NEI) issue(k + 2);
    }

    // ---- epilogue: bias (+tvec) (+resid), direct STG ------------------------
    #pragma unroll
    for (int ti = 0; ti < 2; ti++) {
        const int r0 = base + w * 32 + ti * 16 + g;
        const int r1 = r0 + 8;
        const float* tvp0 = nullptr; const float* tvp1 = nullptr;
        if (tvec) {
            tvp0 = tvec + (size_t)bid[r0] * 64;
            tvp1 = tvec + (size_t)bid[r1] * 64;
        }
        #pragma unroll
        for (int c = 0; c < 8; c++) {
            int co = c * 8 + 2 * tig;
            float2 bb = *reinterpret_cast<const float2*>(bias + co);
            float2 o0 = make_float2(acc[ti][c][0] + bb.x, acc[ti][c][1] + bb.y);
            float2 o1 = make_float2(acc[ti][c][2] + bb.x, acc[ti][c][3] + bb.y);
            if (tvec) {
                float2 tv0 = *reinterpret_cast<const float2*>(tvp0 + co);
                float2 tv1 = *reinterpret_cast<const float2*>(tvp1 + co);
                o0.x += tv0.x; o0.y += tv0.y;
                o1.x += tv1.x; o1.y += tv1.y;
            }
            if (resid) {
                float2 q0 = *reinterpret_cast<const float2*>(resid + (size_t)r0 * 64 + co);
                float2 q1 = *reinterpret_cast<const float2*>(resid + (size_t)r1 * 64 + co);
                o0.x += q0.x; o0.y += q0.y;
                o1.x += q1.x; o1.y += q1.y;
            }
            *reinterpret_cast<float2*>(out + (size_t)r0 * 64 + co) = o0;
            *reinterpret_cast<float2*>(out + (size_t)r1 * 64 + co) = o1;
        }
    }
}

// ---------------- launch ------------------------------------------------------
extern "C" void kernel_launch(void* const* d_in, const int* in_sizes, int n_in,
                              void* d_out, int out_size) {
    const float* x    = (const float*)d_in[0];
    const float* temb = (const float*)d_in[1];
    const int*   bid  = (const int*)  d_in[2];
    const int*   nei  = (const int*)  d_in[3];
    const float* ga1  = (const float*)d_in[4];
    const float* be1  = (const float*)d_in[5];
    const float* W1   = (const float*)d_in[6];
    const float* b1   = (const float*)d_in[7];
    const float* Wt   = (const float*)d_in[8];
    const float* bt   = (const float*)d_in[9];
    const float* ga2  = (const float*)d_in[10];
    const float* be2  = (const float*)d_in[11];
    const float* W2   = (const float*)d_in[12];
    const float* b2   = (const float*)d_in[13];
    float* out = (float*)d_out;

    float *h1, *h2, *sum, *ssq, *cnt, *scale, *shift, *tvec;
    float2 *w1f, *w2f;
    cudaGetSymbolAddress((void**)&h1,    g_h1);
    cudaGetSymbolAddress((void**)&h2,    g_h2);
    cudaGetSymbolAddress((void**)&w1f,   g_w1f);
    cudaGetSymbolAddress((void**)&w2f,   g_w2f);
    cudaGetSymbolAddress((void**)&sum,   g_sum);
    cudaGetSymbolAddress((void**)&ssq,   g_ssq);
    cudaGetSymbolAddress((void**)&cnt,   g_cnt);
    cudaGetSymbolAddress((void**)&scale, g_scale);
    cudaGetSymbolAddress((void**)&shift, g_shift);
    cudaGetSymbolAddress((void**)&tvec,  g_tvec);

    cudaFuncSetAttribute(conv_mma_kernel,
                         cudaFuncAttributeMaxDynamicSharedMemorySize, SM_TOTAL);

    const int statsBlocks = N_NODES / 512;
    const int naBlocks    = (N_NODES * 16) / 256;
    const int convBlocks  = N_NODES / TN;                    // 512
    const int prepBlocks  = (K_NEI * 2048 + 255) / 256;      // 216

    // independent prep
    prep_w_kernel<<<prepBlocks, 256>>>(W1, w1f);
    prep_w_kernel<<<prepBlocks, 256>>>(W2, w2f);
    time_kernel<<<1, 512>>>(temb, Wt, bt, tvec);

    // GN1 -> silu -> h1 (tf32-rounded)
    zero_kernel<<<1, 512>>>(sum, ssq, cnt);
    stats_kernel<<<statsBlocks, 256>>>(x, bid, sum, ssq, cnt, 1);
    finalize_kernel<<<1, 512>>>(sum, ssq, cnt, ga1, be1, scale, shift, 1);
    normact_kernel<<<naBlocks, 256>>>((const float4*)x, bid,
                                      (const float4*)scale, (const float4*)shift,
                                      (float4*)h1);

    // conv1 (tf32 mma.sync) + t[batch] -> h2
    conv_mma_kernel<<<convBlocks, 256, SM_TOTAL>>>(h1, nei, w1f, b1, tvec, bid, nullptr, h2);

    // GN2 -> silu -> h1
    stats_kernel<<<statsBlocks, 256>>>(h2, bid, sum, ssq, cnt, 0);
    finalize_kernel<<<1, 512>>>(sum, ssq, cnt, ga2, be2, scale, shift, 0);
    normact_kernel<<<naBlocks, 256>>>((const float4*)h2, bid,
                                      (const float4*)scale, (const float4*)shift,
                                      (float4*)h1);

    // conv2 (tf32 mma.sync) + residual -> out
    conv_mma_kernel<<<convBlocks, 256, SM_TOTAL>>>(h1, nei, w2f, b2, nullptr, bid, x, out);
}

// round 7
// speedup vs baseline: 1.8102x; 1.8102x over previous
#include <cuda_runtime.h>
#include <cuda_fp16.h>
#include <cstdint>

#define N_NODES 131072
#define C_DIM   64
#define K_NEI   27
#define B_DIM   8
#define EMB_DIM 512
#define GN_EPS  1e-5f

// ---------------- scratch (device globals; no allocation allowed) -----------
__device__ __half g_h1[N_NODES * C_DIM];   // fp16 activations for MMA
__device__ float  g_h2[N_NODES * C_DIM];
__device__ uint2  g_w1f[K_NEI * 1024];     // W1 fp16 B-fragments
__device__ uint2  g_w2f[K_NEI * 1024];     // W2 fp16 B-fragments
__device__ float  g_sum[B_DIM * C_DIM];
__device__ float  g_ssq[B_DIM * C_DIM];
__device__ float  g_cnt[B_DIM];
__device__ float  g_scale[B_DIM * C_DIM];
__device__ float  g_shift[B_DIM * C_DIM];
__device__ float  g_tvec[B_DIM * C_DIM];

// ---------------- helpers ----------------------------------------------------
__device__ __forceinline__ uint32_t smem_u32(const void* p) {
    uint32_t a;
    asm("{ .reg .u64 t; cvta.to.shared.u64 t, %1; cvt.u32.u64 %0, t; }" : "=r"(a) : "l"(p));
    return a;
}
__device__ __forceinline__ void cp16(uint32_t dst, const void* src) {
    asm volatile("cp.async.cg.shared.global [%0], [%1], 16;" :: "r"(dst), "l"(src) : "memory");
}
__device__ __forceinline__ void cp_commit() {
    asm volatile("cp.async.commit_group;" ::: "memory");
}
template <int N>
__device__ __forceinline__ void cp_wait() {
    asm volatile("cp.async.wait_group %0;" :: "n"(N) : "memory");
}
__device__ __forceinline__ void ldmatrix4(uint32_t* r, uint32_t addr) {
    asm volatile("ldmatrix.sync.aligned.m8n8.x4.shared.b16 {%0,%1,%2,%3}, [%4];"
                 : "=r"(r[0]), "=r"(r[1]), "=r"(r[2]), "=r"(r[3]) : "r"(addr));
}
__device__ __forceinline__ void mma_f16(float* d, const uint32_t* a, uint32_t b0, uint32_t b1) {
    asm volatile(
        "mma.sync.aligned.m16n8k16.row.col.f32.f16.f16.f32 "
        "{%0,%1,%2,%3}, {%4,%5,%6,%7}, {%8,%9}, {%0,%1,%2,%3};"
        : "+f"(d[0]), "+f"(d[1]), "+f"(d[2]), "+f"(d[3])
        : "r"(a[0]), "r"(a[1]), "r"(a[2]), "r"(a[3]), "r"(b0), "r"(b1));
}
__device__ __forceinline__ float silu_f(float v) { return v / (1.0f + __expf(-v)); }
__device__ __forceinline__ uint32_t pack_h2(float x, float y) {
    __half2 h = __floats2half2_rn(x, y);
    return *reinterpret_cast<uint32_t*>(&h);
}

// ---------------- GN helper kernels ------------------------------------------
__global__ void zero_kernel(float* gsum, float* gssq, float* gcnt) {
    int i = threadIdx.x;
    gsum[i] = 0.0f; gssq[i] = 0.0f;
    if (i < B_DIM) gcnt[i] = 0.0f;
}

__global__ void stats_kernel(const float* __restrict__ in, const int* __restrict__ bid,
                             float* __restrict__ gsum, float* __restrict__ gssq,
                             float* __restrict__ gcnt, int do_cnt) {
    const int NPB = 512;
    int c = threadIdx.x & 63, r = threadIdx.x >> 6;
    int base = blockIdx.x * NPB;
    float s = 0.0f, ss = 0.0f, cl = 0.0f;
    int cur = bid[base + r];
    for (int i = 0; i < NPB / 4; i++) {
        int n = base + i * 4 + r;
        int b = bid[n];
        if (b != cur) {
            atomicAdd(&gsum[cur * 64 + c], s);
            atomicAdd(&gssq[cur * 64 + c], ss);
            if (do_cnt && c == 0) atomicAdd(&gcnt[cur], cl);
            s = 0.0f; ss = 0.0f; cl = 0.0f; cur = b;
        }
        float v = in[(size_t)n * 64 + c];
        s += v; ss += v * v; cl += 1.0f;
    }
    atomicAdd(&gsum[cur * 64 + c], s);
    atomicAdd(&gssq[cur * 64 + c], ss);
    if (do_cnt && c == 0) atomicAdd(&gcnt[cur], cl);
}

__global__ void finalize_kernel(float* __restrict__ gsum, float* __restrict__ gssq,
                                const float* __restrict__ gcnt,
                                const float* __restrict__ gamma, const float* __restrict__ beta,
                                float* __restrict__ scale, float* __restrict__ shift,
                                int zero_after) {
    int i = threadIdx.x;
    int b = i >> 6, c = i & 63;
    int g0 = c & ~1;
    float denom = gcnt[b] * 2.0f;
    float m = (gsum[b * 64 + g0] + gsum[b * 64 + g0 + 1]) / denom;
    float v = (gssq[b * 64 + g0] + gssq[b * 64 + g0 + 1]) / denom - m * m;
    float rs = rsqrtf(v + GN_EPS);
    float sc = gamma[c] * rs;
    scale[i] = sc;
    shift[i] = beta[c] - m * sc;
    if (zero_after) {
        __syncthreads();
        gsum[i] = 0.0f;
        gssq[i] = 0.0f;
    }
}

// normalize + SiLU -> fp16 output (8 channels / thread)
__global__ void normact_kernel(const float4* __restrict__ in, const int* __restrict__ bid,
                               const float4* __restrict__ scale, const float4* __restrict__ shift,
                               uint4* __restrict__ out) {
    int idx = blockIdx.x * blockDim.x + threadIdx.x;   // N*8
    int n = idx >> 3, q = idx & 7;
    int b = bid[n];
    float4 v0 = in[n * 16 + q * 2];
    float4 v1 = in[n * 16 + q * 2 + 1];
    float4 sc0 = scale[b * 16 + q * 2], sc1 = scale[b * 16 + q * 2 + 1];
    float4 sh0 = shift[b * 16 + q * 2], sh1 = shift[b * 16 + q * 2 + 1];
    float r0 = silu_f(v0.x * sc0.x + sh0.x);
    float r1 = silu_f(v0.y * sc0.y + sh0.y);
    float r2 = silu_f(v0.z * sc0.z + sh0.z);
    float r3 = silu_f(v0.w * sc0.w + sh0.w);
    float r4 = silu_f(v1.x * sc1.x + sh1.x);
    float r5 = silu_f(v1.y * sc1.y + sh1.y);
    float r6 = silu_f(v1.z * sc1.z + sh1.z);
    float r7 = silu_f(v1.w * sc1.w + sh1.w);
    out[idx] = make_uint4(pack_h2(r0, r1), pack_h2(r2, r3),
                          pack_h2(r4, r5), pack_h2(r6, r7));
}

__global__ void time_kernel(const float* __restrict__ emb, const float* __restrict__ Wt,
                            const float* __restrict__ bt, float* __restrict__ tout) {
    __shared__ float se[B_DIM * EMB_DIM];
    int t = threadIdx.x;
    for (int i = t; i < B_DIM * EMB_DIM; i += 512) se[i] = silu_f(emb[i]);
    __syncthreads();
    int b = t >> 6, co = t & 63;
    float acc = bt[co];
    const float* e = se + b * EMB_DIM;
    #pragma unroll 8
    for (int k = 0; k < EMB_DIM; k++) acc += e[k] * Wt[k * 64 + co];
    tout[t] = acc;
}

// ---------------- weight prep: W[k][ci][co] -> fp16 B-fragment order ---------
// per k: 4 ksteps x 8 cotiles x 32 lanes, uint2 {b0=h2(W[ci0],W[ci0+1]), b1=h2(W[ci0+8],W[ci0+9])}
__global__ void prep_w_kernel(const float* __restrict__ W, uint2* __restrict__ Wf) {
    int i = blockIdx.x * 256 + threadIdx.x;      // over K_NEI*1024
    if (i >= K_NEI * 1024) return;
    int k = i >> 10;
    int r = i & 1023;
    int grp = r >> 5, lane = r & 31;
    int ks = grp >> 3, c = grp & 7;
    int gid = lane >> 2, tig = lane & 3;
    int ci0 = ks * 16 + 2 * tig;
    int co = c * 8 + gid;
    const float* wk = W + (size_t)k * 4096;
    uint2 v;
    v.x = pack_h2(wk[ci0 * 64 + co],       wk[(ci0 + 1) * 64 + co]);
    v.y = pack_h2(wk[(ci0 + 8) * 64 + co], wk[(ci0 + 9) * 64 + co]);
    Wf[i] = v;
}

// ---------------- fp16 mma.sync gather-conv ----------------------------------
// 256 nodes/block, 256 threads (8 warps x 32 rows), 2 CTAs/SM.
// fp16 rows = 128B; warp-coalesced cp.async staging (4 rows / warp-op);
// XOR-swizzled A buffer read via ldmatrix.x4.
#define TN        256
#define WS_OFF    0                           // uint2 ws[2][1024] : 16KB
#define XS_OFF    16384                       // half  xs[2][256*64]: 64KB
#define NB_OFF    (16384 + 65536)             // int snb[27][256]  : 27648B
#define SM_TOTAL  (NB_OFF + K_NEI * TN * 4)   // 109568

__global__ void __launch_bounds__(256, 2) conv_mma_kernel(
    const __half* __restrict__ h, const int* __restrict__ neigh,
    const uint2* __restrict__ wf, const float* __restrict__ bias,
    const float* __restrict__ tvec, const int* __restrict__ bid,
    const float* __restrict__ resid, float* __restrict__ out)
{
    extern __shared__ char smem[];
    uint2* ws = reinterpret_cast<uint2*>(smem + WS_OFF);
    int*   snb = reinterpret_cast<int*>(smem + NB_OFF);
    const uint32_t ws_sm = smem_u32(smem + WS_OFF);
    const uint32_t xs_sm = smem_u32(smem + XS_OFF);

    const int t = threadIdx.x;
    const int w = t >> 5, l = t & 31;
    const int base = blockIdx.x * TN;

    // ---- transpose-load neighbor ids: snb[k][row] (coalesced gmem read) ----
    {
        const int* nsrc = neigh + (size_t)base * K_NEI;
        for (int i = t; i < TN * K_NEI; i += 256) {
            int node = i / K_NEI;
            int kk = i - node * K_NEI;
            snb[kk * TN + node] = nsrc[i];
        }
    }
    __syncthreads();

    float acc[2][8][4];
    #pragma unroll
    for (int ti = 0; ti < 2; ti++)
        #pragma unroll
        for (int c = 0; c < 8; c++)
            #pragma unroll
            for (int j = 0; j < 4; j++) acc[ti][c][j] = 0.0f;

    // ldmatrix addresses (per lane), buf 0; buf 1 adds 32768
    uint32_t amat[2][4];
    {
        int row_local = l & 15;                 // lanes 0-7:m0 rows, 8-15:m1, 16-23:m2, 24-31:m3
        int hi = l >> 4;                        // chunk high bit (m2/m3)
        #pragma unroll
        for (int ti = 0; ti < 2; ti++) {
            int row = w * 32 + ti * 16 + row_local;
            #pragma unroll
            for (int ks = 0; ks < 4; ks++) {
                int chunk = 2 * ks + hi;
                amat[ti][ks] = xs_sm + row * 128 + (((chunk ^ (l & 7))) << 4);
            }
        }
    }

    const int grow4 = l >> 3;      // 0..3: row within 4-row warp-op
    const int chunk = l & 7;       // 16B chunk within the 128B row

    // ---- stage k into buffer (k&1): warp-coalesced ------------------------
    auto issue = [&](int k) {
        const int buf = k & 1;
        // weights: 8KB linear, 2x16B per thread
        {
            const char* src = reinterpret_cast<const char*>(wf + (size_t)k * 1024) + t * 32;
            uint32_t dst = ws_sm + buf * 8192 + t * 32;
            cp16(dst, src);
            cp16(dst + 16, src + 16);
        }
        // gather: warp w stages rows w*32..w*32+31; 4 rows per instruction
        {
            const int* nbk = snb + k * TN;
            #pragma unroll
            for (int i = 0; i < 8; i++) {
                int row = w * 32 + i * 4 + grow4;
                int nbv = nbk[row];
                const char* src = reinterpret_cast<const char*>(h + (size_t)nbv * 64)
                                  + chunk * 16;
                uint32_t dst = xs_sm + buf * 32768 + row * 128
                               + ((chunk ^ (row & 7)) << 4);
                cp16(dst, src);
            }
        }
        cp_commit();
    };

    issue(0);
    issue(1);

    for (int k = 0; k < K_NEI; k++) {
        cp_wait<1>();          // group k complete
        __syncthreads();

        const int buf = k & 1;
        const uint32_t bufoff = buf * 32768;
        const uint2* wb = ws + buf * 1024;

        #pragma unroll
        for (int ks = 0; ks < 4; ks++) {
            uint32_t a0[4], a1[4];
            ldmatrix4(a0, amat[0][ks] + bufoff);
            ldmatrix4(a1, amat[1][ks] + bufoff);
            #pragma unroll
            for (int c = 0; c < 8; c++) {
                uint2 b = wb[(ks * 8 + c) * 32 + l];
                mma_f16(acc[0][c], a0, b.x, b.y);
                mma_f16(acc[1][c], a1, b.x, b.y);
            }
        }
        __syncthreads();       // all warps done with buf before refill
        if (k + 2 < K_NEI) issue(k + 2);
    }

    // ---- epilogue: bias (+tvec) (+resid), direct STG ------------------------
    const int g = l >> 2, tig = l & 3;
    #pragma unroll
    for (int ti = 0; ti < 2; ti++) {
        const int r0 = base + w * 32 + ti * 16 + g;
        const int r1 = r0 + 8;
        const float* tvp0 = nullptr; const float* tvp1 = nullptr;
        if (tvec) {
            tvp0 = tvec + (size_t)bid[r0] * 64;
            tvp1 = tvec + (size_t)bid[r1] * 64;
        }
        #pragma unroll
        for (int c = 0; c < 8; c++) {
            int co = c * 8 + 2 * tig;
            float2 bb = *reinterpret_cast<const float2*>(bias + co);
            float2 o0 = make_float2(acc[ti][c][0] + bb.x, acc[ti][c][1] + bb.y);
            float2 o1 = make_float2(acc[ti][c][2] + bb.x, acc[ti][c][3] + bb.y);
            if (tvec) {
                float2 tv0 = *reinterpret_cast<const float2*>(tvp0 + co);
                float2 tv1 = *reinterpret_cast<const float2*>(tvp1 + co);
                o0.x += tv0.x; o0.y += tv0.y;
                o1.x += tv1.x; o1.y += tv1.y;
            }
            if (resid) {
                float2 q0 = *reinterpret_cast<const float2*>(resid + (size_t)r0 * 64 + co);
                float2 q1 = *reinterpret_cast<const float2*>(resid + (size_t)r1 * 64 + co);
                o0.x += q0.x; o0.y += q0.y;
                o1.x += q1.x; o1.y += q1.y;
            }
            *reinterpret_cast<float2*>(out + (size_t)r0 * 64 + co) = o0;
            *reinterpret_cast<float2*>(out + (size_t)r1 * 64 + co) = o1;
        }
    }
}

// ---------------- launch ------------------------------------------------------
extern "C" void kernel_launch(void* const* d_in, const int* in_sizes, int n_in,
                              void* d_out, int out_size) {
    const float* x    = (const float*)d_in[0];
    const float* temb = (const float*)d_in[1];
    const int*   bid  = (const int*)  d_in[2];
    const int*   nei  = (const int*)  d_in[3];
    const float* ga1  = (const float*)d_in[4];
    const float* be1  = (const float*)d_in[5];
    const float* W1   = (const float*)d_in[6];
    const float* b1   = (const float*)d_in[7];
    const float* Wt   = (const float*)d_in[8];
    const float* bt   = (const float*)d_in[9];
    const float* ga2  = (const float*)d_in[10];
    const float* be2  = (const float*)d_in[11];
    const float* W2   = (const float*)d_in[12];
    const float* b2   = (const float*)d_in[13];
    float* out = (float*)d_out;

    __half* h1;
    float *h2, *sum, *ssq, *cnt, *scale, *shift, *tvec;
    uint2 *w1f, *w2f;
    cudaGetSymbolAddress((void**)&h1,    g_h1);
    cudaGetSymbolAddress((void**)&h2,    g_h2);
    cudaGetSymbolAddress((void**)&w1f,   g_w1f);
    cudaGetSymbolAddress((void**)&w2f,   g_w2f);
    cudaGetSymbolAddress((void**)&sum,   g_sum);
    cudaGetSymbolAddress((void**)&ssq,   g_ssq);
    cudaGetSymbolAddress((void**)&cnt,   g_cnt);
    cudaGetSymbolAddress((void**)&scale, g_scale);
    cudaGetSymbolAddress((void**)&shift, g_shift);
    cudaGetSymbolAddress((void**)&tvec,  g_tvec);

    cudaFuncSetAttribute(conv_mma_kernel,
                         cudaFuncAttributeMaxDynamicSharedMemorySize, SM_TOTAL);

    const int statsBlocks = N_NODES / 512;
    const int naBlocks    = (N_NODES * 8) / 256;             // 4096
    const int convBlocks  = N_NODES / TN;                    // 512
    const int prepBlocks  = (K_NEI * 1024 + 255) / 256;      // 108

    // independent prep
    prep_w_kernel<<<prepBlocks, 256>>>(W1, w1f);
    prep_w_kernel<<<prepBlocks, 256>>>(W2, w2f);
    time_kernel<<<1, 512>>>(temb, Wt, bt, tvec);

    // GN1 -> silu -> h1 (fp16)
    zero_kernel<<<1, 512>>>(sum, ssq, cnt);
    stats_kernel<<<statsBlocks, 256>>>(x, bid, sum, ssq, cnt, 1);
    finalize_kernel<<<1, 512>>>(sum, ssq, cnt, ga1, be1, scale, shift, 1);
    normact_kernel<<<naBlocks, 256>>>((const float4*)x, bid,
                                      (const float4*)scale, (const float4*)shift,
                                      (uint4*)h1);

    // conv1 (fp16 mma.sync) + t[batch] -> h2
    conv_mma_kernel<<<convBlocks, 256, SM_TOTAL>>>(h1, nei, w1f, b1, tvec, bid, nullptr, h2);

    // GN2 -> silu -> h1 (fp16)
    stats_kernel<<<statsBlocks, 256>>>(h2, bid, sum, ssq, cnt, 0);
    finalize_kernel<<<1, 512>>>(sum, ssq, cnt, ga2, be2, scale, shift, 0);
    normact_kernel<<<naBlocks, 256>>>((const float4*)h2, bid,
                                      (const float4*)scale, (const float4*)shift,
                                      (uint4*)h1);

    // conv2 (fp16 mma.sync) + residual -> out
    conv_mma_kernel<<<convBlocks, 256, SM_TOTAL>>>(h1, nei, w2f, b2, nullptr, bid, x, out);
}